// round 8
// baseline (speedup 1.0000x reference)
#include <cuda_runtime.h>
#include <math.h>

#define DMODEL 768
#define NHEADS 12
#define DH 64
#define NQV 8
#define BBATCH 16
#define PTOK 197
#define NPAIR 256                 // 16*16
#define MKV (BBATCH * PTOK)       // 3152
#define MOUT (NPAIR * NQV)        // 2048

// ---------------- device scratch (no allocation allowed) ----------------
__device__ float g_qn[NQV * DMODEL];
__device__ float g_kvn[MKV * DMODEL];
__device__ float g_m[2 * BBATCH * NHEADS * NQV];
__device__ float g_ssum[2 * BBATCH * NHEADS * NQV];
__device__ float g_V[2 * BBATCH * NHEADS * NQV * DH];
__device__ float g_ca[NPAIR * NHEADS * NQV];
__device__ float g_cb[NPAIR * NHEADS * NQV];
__device__ float g_vals[MOUT * DMODEL];

// ---------------- generic SGEMM: C[M,768] = A[M,768] @ W[768,768]^T + bias ----------------
// 64x64 tile, BK=16, 256 threads, 4x4 register micro-tile per thread.
__global__ void gemm_bias_kernel(const float* __restrict__ A,
                                 const float* __restrict__ W,
                                 const float* __restrict__ bias,
                                 float* __restrict__ C,
                                 int M) {
    const int K = DMODEL;
    const int N = DMODEL;
    __shared__ float sA[16][64];
    __shared__ float sB[16][64];
    int bm = blockIdx.x * 64;
    int bn = blockIdx.y * 64;
    int tid = threadIdx.x;
    int tx = tid & 15;
    int ty = tid >> 4;
    int lr = tid >> 2;          // 0..63 tile row for loads
    int lc = (tid & 3) << 2;    // k offset (float4)
    const float* Ap = A + (size_t)(bm + lr) * K + lc;
    const float* Wp = W + (size_t)(bn + lr) * K + lc;
    bool a_ok = (bm + lr) < M;

    float acc[4][4];
#pragma unroll
    for (int i = 0; i < 4; i++)
#pragma unroll
        for (int j = 0; j < 4; j++) acc[i][j] = 0.f;

    for (int k0 = 0; k0 < K; k0 += 16) {
        float4 av = a_ok ? *(const float4*)(Ap + k0) : make_float4(0.f, 0.f, 0.f, 0.f);
        float4 wv = *(const float4*)(Wp + k0);
        __syncthreads();
        sA[lc + 0][lr] = av.x; sA[lc + 1][lr] = av.y; sA[lc + 2][lr] = av.z; sA[lc + 3][lr] = av.w;
        sB[lc + 0][lr] = wv.x; sB[lc + 1][lr] = wv.y; sB[lc + 2][lr] = wv.z; sB[lc + 3][lr] = wv.w;
        __syncthreads();
#pragma unroll
        for (int k = 0; k < 16; k++) {
            float4 a4 = *(const float4*)&sA[k][ty << 2];
            float4 b4 = *(const float4*)&sB[k][tx << 2];
            float a[4] = {a4.x, a4.y, a4.z, a4.w};
            float b[4] = {b4.x, b4.y, b4.z, b4.w};
#pragma unroll
            for (int i = 0; i < 4; i++)
#pragma unroll
                for (int j = 0; j < 4; j++) acc[i][j] += a[i] * b[j];
        }
    }
#pragma unroll
    for (int i = 0; i < 4; i++) {
        int row = bm + (ty << 2) + i;
        if (row < M) {
#pragma unroll
            for (int j = 0; j < 4; j++) {
                int col = bn + (tx << 2) + j;
                C[(size_t)row * N + col] = acc[i][j] + bias[col];
            }
        }
    }
}

// ---------------- in-place LayerNorm over rows of 768, 256 threads/row ----------------
__global__ void ln_kernel(float* __restrict__ X,
                          const float* __restrict__ w,
                          const float* __restrict__ b) {
    int row = blockIdx.x;
    float* x = X + (size_t)row * DMODEL;
    int tid = threadIdx.x;
    float v0 = x[tid], v1 = x[tid + 256], v2 = x[tid + 512];
    float s = v0 + v1 + v2;
    float sq = v0 * v0 + v1 * v1 + v2 * v2;
    __shared__ float sbuf[16];
#pragma unroll
    for (int o = 16; o; o >>= 1) {
        s  += __shfl_xor_sync(0xffffffffu, s, o);
        sq += __shfl_xor_sync(0xffffffffu, sq, o);
    }
    int warp = tid >> 5, lane = tid & 31;
    if (lane == 0) { sbuf[warp] = s; sbuf[warp + 8] = sq; }
    __syncthreads();
    if (tid < 32) {
        float ss = (lane < 8) ? sbuf[lane] : 0.f;
        float qq = (lane < 8) ? sbuf[lane + 8] : 0.f;
#pragma unroll
        for (int o = 4; o; o >>= 1) {
            ss += __shfl_xor_sync(0xffffffffu, ss, o);
            qq += __shfl_xor_sync(0xffffffffu, qq, o);
        }
        if (lane == 0) { sbuf[0] = ss; sbuf[1] = qq; }
    }
    __syncthreads();
    float mean = sbuf[0] * (1.f / 768.f);
    float var  = sbuf[1] * (1.f / 768.f) - mean * mean;
    float rstd = rsqrtf(var + 1e-5f);
    x[tid]       = (v0 - mean) * rstd * w[tid]       + b[tid];
    x[tid + 256] = (v1 - mean) * rstd * w[tid + 256] + b[tid + 256];
    x[tid + 512] = (v2 - mean) * rstd * w[tid + 512] + b[tid + 512];
}

// ---------------- per-(side,i,head) attention partials ----------------
// side 0: keys = kv[i] + pos[:197];  side 1: keys = kv[i] + pos[197:]
// Outputs per (side,i,h,qi): row-max m, sum of exp(s-m), and V = exp(s-m) @ K
__global__ void attn_pre_kernel(const float* __restrict__ pos) {
    int i = blockIdx.x;      // 16
    int h = blockIdx.y;      // 12
    int side = blockIdx.z;   // 2
    __shared__ float sK[PTOK][33];
    __shared__ float sS[NQV][PTOK];
    __shared__ float sQ[NQV][64];
    int tid = threadIdx.x;
    int lane = tid & 31;
    int warp = tid >> 5;     // warp == qi (8 warps)

    for (int e = tid; e < NQV * 64; e += 256)
        sQ[e >> 6][e & 63] = g_qn[(e >> 6) * DMODEL + h * 64 + (e & 63)];

    float acc[7];
#pragma unroll
    for (int k = 0; k < 7; k++) acc[k] = 0.f;

    // ---- scores: two 32-wide d chunks ----
    for (int c = 0; c < 2; c++) {
        __syncthreads();
        for (int e = tid; e < PTOK * 32; e += 256) {
            int p = e >> 5, d = e & 31;
            sK[p][d] = g_kvn[(size_t)(i * PTOK + p) * DMODEL + h * 64 + c * 32 + d]
                     + pos[(size_t)(side * PTOK + p) * DMODEL + h * 64 + c * 32 + d];
        }
        __syncthreads();
#pragma unroll
        for (int d = 0; d < 32; d++) {
            float qv = sQ[warp][c * 32 + d];
#pragma unroll
            for (int k = 0; k < 7; k++) {
                int p = lane + (k << 5);
                if (p < PTOK) acc[k] += sK[p][d] * qv;
            }
        }
    }

    // ---- softmax stats (scale = 1/sqrt(64) = 0.125) ----
    float m = -INFINITY;
#pragma unroll
    for (int k = 0; k < 7; k++) {
        int p = lane + (k << 5);
        if (p < PTOK) m = fmaxf(m, acc[k] * 0.125f);
    }
#pragma unroll
    for (int o = 16; o; o >>= 1) m = fmaxf(m, __shfl_xor_sync(0xffffffffu, m, o));
    float ssum = 0.f;
#pragma unroll
    for (int k = 0; k < 7; k++) {
        int p = lane + (k << 5);
        if (p < PTOK) {
            float e = expf(acc[k] * 0.125f - m);
            sS[warp][p] = e;
            ssum += e;
        }
    }
#pragma unroll
    for (int o = 16; o; o >>= 1) ssum += __shfl_xor_sync(0xffffffffu, ssum, o);
    int sidx = ((side * BBATCH + i) * NHEADS + h) * NQV + warp;
    if (lane == 0) { g_m[sidx] = m; g_ssum[sidx] = ssum; }

    // ---- unnormalized values: V[qi][d] = sum_p E[qi][p] * K[p][d] ----
    for (int c = 0; c < 2; c++) {
        __syncthreads();
        for (int e = tid; e < PTOK * 32; e += 256) {
            int p = e >> 5, d = e & 31;
            sK[p][d] = g_kvn[(size_t)(i * PTOK + p) * DMODEL + h * 64 + c * 32 + d]
                     + pos[(size_t)(side * PTOK + p) * DMODEL + h * 64 + c * 32 + d];
        }
        __syncthreads();
        float vacc = 0.f;
        for (int p = 0; p < PTOK; p++) vacc += sS[warp][p] * sK[p][lane];
        g_V[(size_t)sidx * 64 + c * 32 + lane] = vacc;
    }
}

// ---------------- per-pair renormalization coefficients ----------------
__global__ void coef_kernel() {
    int idx = blockIdx.x * 256 + threadIdx.x;   // NPAIR*12*8 = 24576
    if (idx >= NPAIR * NHEADS * NQV) return;
    int qi = idx & 7;
    int h  = (idx >> 3) % NHEADS;
    int b  = idx / (NHEADS * NQV);
    int i = b >> 4, j = b & 15;
    int i1 = ((0 * BBATCH + i) * NHEADS + h) * NQV + qi;
    int i2 = ((1 * BBATCH + j) * NHEADS + h) * NQV + qi;
    float m1 = g_m[i1], m2 = g_m[i2];
    float s1 = g_ssum[i1], s2 = g_ssum[i2];
    float mm = fmaxf(m1, m2);
    float e1 = expf(m1 - mm), e2 = expf(m2 - mm);
    float Z = s1 * e1 + s2 * e2;
    float inv = 1.f / Z;
    g_ca[idx] = e1 * inv;
    g_cb[idx] = e2 * inv;
}

// ---------------- combine: vals[b,qi, h*64+d] = ca*V1 - cb*V2 ----------------
__global__ void combine_kernel() {
    int t = blockIdx.x * 256 + threadIdx.x;     // MOUT * 768 = 1,572,864
    int col = t % DMODEL;
    int row = t / DMODEL;
    int h = col >> 6, d = col & 63;
    int b = row >> 3, qi = row & 7;
    int i = b >> 4, j = b & 15;
    int cidx = (b * NHEADS + h) * NQV + qi;
    float v1 = g_V[((size_t)((0 * BBATCH + i) * NHEADS + h) * NQV + qi) * 64 + d];
    float v2 = g_V[((size_t)((1 * BBATCH + j) * NHEADS + h) * NQV + qi) * 64 + d];
    g_vals[t] = g_ca[cidx] * v1 - g_cb[cidx] * v2;
}

// ---------------- launch ----------------
extern "C" void kernel_launch(void* const* d_in, const int* in_sizes, int n_in,
                              void* d_out, int out_size) {
    const float* q_x    = (const float*)d_in[0];
    const float* kv_x   = (const float*)d_in[1];
    const float* pos    = (const float*)d_in[2];
    const float* q_w    = (const float*)d_in[3];
    const float* q_b    = (const float*)d_in[4];
    const float* kv_w   = (const float*)d_in[5];
    const float* kv_b   = (const float*)d_in[6];
    const float* out_w  = (const float*)d_in[7];
    const float* out_b  = (const float*)d_in[8];
    const float* lnq_w  = (const float*)d_in[9];
    const float* lnq_b  = (const float*)d_in[10];
    const float* lnkv_w = (const float*)d_in[11];
    const float* lnkv_b = (const float*)d_in[12];
    float* out = (float*)d_out;

    float *qn, *kvn, *vals;
    cudaGetSymbolAddress((void**)&qn, g_qn);
    cudaGetSymbolAddress((void**)&kvn, g_kvn);
    cudaGetSymbolAddress((void**)&vals, g_vals);

    // q path: Linear + LN  (M=8)
    gemm_bias_kernel<<<dim3(1, 12), 256>>>(q_x, q_w, q_b, qn, NQV);
    ln_kernel<<<NQV, 256>>>(qn, lnq_w, lnq_b);

    // kv path: Linear + LN (M=3152)
    gemm_bias_kernel<<<dim3((MKV + 63) / 64, 12), 256>>>(kv_x, kv_w, kv_b, kvn, MKV);
    ln_kernel<<<MKV, 256>>>(kvn, lnkv_w, lnkv_b);

    // per-(side,i,head) attention partials
    attn_pre_kernel<<<dim3(BBATCH, NHEADS, 2), 256>>>(pos);

    // pair renormalization + combine
    coef_kernel<<<(NPAIR * NHEADS * NQV + 255) / 256, 256>>>();
    combine_kernel<<<(MOUT * DMODEL) / 256, 256>>>();

    // output projection (M=2048) straight into d_out
    gemm_bias_kernel<<<dim3(MOUT / 64, 12), 256>>>(vals, out_w, out_b, out, MOUT);
}

// round 9
// speedup vs baseline: 1.3604x; 1.3604x over previous
#include <cuda_runtime.h>
#include <math.h>

#define DMODEL 768
#define NHEADS 12
#define DH 64
#define NQV 8
#define BBATCH 16
#define PTOK 197
#define NPAIR 256                 // 16*16
#define MKV (BBATCH * PTOK)       // 3152
#define MOUT (NPAIR * NQV)        // 2048

typedef unsigned long long ull;

// ---------------- device scratch (no allocation allowed) ----------------
__device__ float g_qn[NQV * DMODEL];
__device__ float g_kvn[MKV * DMODEL];
__device__ float g_m[2 * BBATCH * NHEADS * NQV];
__device__ float g_ssum[2 * BBATCH * NHEADS * NQV];
__device__ float g_V[2 * BBATCH * NHEADS * NQV * DH];
__device__ float g_ca[NPAIR * NHEADS * NQV];
__device__ float g_cb[NPAIR * NHEADS * NQV];
__device__ float g_Y[2 * BBATCH * NHEADS * NQV * DMODEL];   // 9.4 MB

// ---------------- packed f32x2 helpers ----------------
__device__ __forceinline__ void ffma2(ull& d, ull a, ull b) {
    asm("fma.rn.f32x2 %0, %1, %2, %0;" : "+l"(d) : "l"(a), "l"(b));
}
__device__ __forceinline__ ull pk(float x) {
    ull r; asm("mov.b64 %0, {%1, %1};" : "=l"(r) : "f"(x)); return r;
}
__device__ __forceinline__ void unpk(float& lo, float& hi, ull v) {
    asm("mov.b64 {%0, %1}, %2;" : "=f"(lo), "=f"(hi) : "l"(v));
}

// ---------------- f32x2 SGEMM: C[M,768] = A[M,768] @ W[768,768]^T + bias --------
// 128x128 tile, BK=16, 256 threads, 8x8 microtile, accumulators packed along M.
__global__ __launch_bounds__(256) void gemm_f32x2_kernel(
        const float* __restrict__ A, const float* __restrict__ W,
        const float* __restrict__ bias, float* __restrict__ C, int M) {
    __shared__ float sA[16][128];
    __shared__ float sB[16][128];
    const int bm = blockIdx.x * 128, bn = blockIdx.y * 128;
    const int tid = threadIdx.x;
    const int tx = tid & 15, ty = tid >> 4;       // n0 = tx*8, m0 = ty*8
    const int lr = tid >> 1, lk = (tid & 1) * 8;  // loader: row lr, k offset lk
    const float* Ap = A + (size_t)(bm + lr) * DMODEL + lk;
    const float* Wp = W + (size_t)(bn + lr) * DMODEL + lk;
    const bool a_ok = (bm + lr) < M;

    ull acc[4][8];
#pragma unroll
    for (int i = 0; i < 4; i++)
#pragma unroll
        for (int j = 0; j < 8; j++) acc[i][j] = 0ull;

    for (int k0 = 0; k0 < DMODEL; k0 += 16) {
        float4 a0 = a_ok ? *(const float4*)(Ap + k0)     : make_float4(0,0,0,0);
        float4 a1 = a_ok ? *(const float4*)(Ap + k0 + 4) : make_float4(0,0,0,0);
        float4 w0 = *(const float4*)(Wp + k0);
        float4 w1 = *(const float4*)(Wp + k0 + 4);
        __syncthreads();
        sA[lk + 0][lr] = a0.x; sA[lk + 1][lr] = a0.y; sA[lk + 2][lr] = a0.z; sA[lk + 3][lr] = a0.w;
        sA[lk + 4][lr] = a1.x; sA[lk + 5][lr] = a1.y; sA[lk + 6][lr] = a1.z; sA[lk + 7][lr] = a1.w;
        sB[lk + 0][lr] = w0.x; sB[lk + 1][lr] = w0.y; sB[lk + 2][lr] = w0.z; sB[lk + 3][lr] = w0.w;
        sB[lk + 4][lr] = w1.x; sB[lk + 5][lr] = w1.y; sB[lk + 6][lr] = w1.z; sB[lk + 7][lr] = w1.w;
        __syncthreads();
#pragma unroll
        for (int k = 0; k < 16; k++) {
            ull a2[4];
#pragma unroll
            for (int i = 0; i < 4; i++)
                a2[i] = *(const ull*)&sA[k][ty * 8 + 2 * i];
            float4 b0 = *(const float4*)&sB[k][tx * 8];
            float4 b1 = *(const float4*)&sB[k][tx * 8 + 4];
            ull bb[8];
            bb[0] = pk(b0.x); bb[1] = pk(b0.y); bb[2] = pk(b0.z); bb[3] = pk(b0.w);
            bb[4] = pk(b1.x); bb[5] = pk(b1.y); bb[6] = pk(b1.z); bb[7] = pk(b1.w);
#pragma unroll
            for (int i = 0; i < 4; i++)
#pragma unroll
                for (int j = 0; j < 8; j++) ffma2(acc[i][j], a2[i], bb[j]);
        }
    }

    float4 bi0 = *(const float4*)&bias[bn + tx * 8];
    float4 bi1 = *(const float4*)&bias[bn + tx * 8 + 4];
    const float bv[8] = {bi0.x, bi0.y, bi0.z, bi0.w, bi1.x, bi1.y, bi1.z, bi1.w};
#pragma unroll
    for (int i = 0; i < 4; i++) {
        float lo[8], hi[8];
#pragma unroll
        for (int j = 0; j < 8; j++) unpk(lo[j], hi[j], acc[i][j]);
        int r0 = bm + ty * 8 + 2 * i;
        if (r0 < M) {
            float4* p = (float4*)&C[(size_t)r0 * DMODEL + bn + tx * 8];
            p[0] = make_float4(lo[0] + bv[0], lo[1] + bv[1], lo[2] + bv[2], lo[3] + bv[3]);
            p[1] = make_float4(lo[4] + bv[4], lo[5] + bv[5], lo[6] + bv[6], lo[7] + bv[7]);
        }
        if (r0 + 1 < M) {
            float4* p = (float4*)&C[(size_t)(r0 + 1) * DMODEL + bn + tx * 8];
            p[0] = make_float4(hi[0] + bv[0], hi[1] + bv[1], hi[2] + bv[2], hi[3] + bv[3]);
            p[1] = make_float4(hi[4] + bv[4], hi[5] + bv[5], hi[6] + bv[6], hi[7] + bv[7]);
        }
    }
}

// ---------------- q projection: qn[8,768] = q_x @ q_w^T + q_b ----------------
// 24 blocks x 256 threads; 8 threads share an n-column, thread handles (q,n).
__global__ void qproj_kernel(const float* __restrict__ q_x,
                             const float* __restrict__ q_w,
                             const float* __restrict__ q_b) {
    __shared__ float sq[NQV * DMODEL];   // 24 KB
    int tid = threadIdx.x;
    for (int e = tid; e < NQV * DMODEL; e += 256) sq[e] = q_x[e];
    __syncthreads();
    int idx = blockIdx.x * 256 + tid;     // 0..6143
    int n = idx >> 3, q = idx & 7;
    const float* wp = q_w + (size_t)n * DMODEL;
    const float* xp = sq + q * DMODEL;
    float acc = 0.f;
#pragma unroll 8
    for (int d4 = 0; d4 < DMODEL / 4; d4++) {
        float4 w4 = *(const float4*)(wp + d4 * 4);
        float4 x4 = *(const float4*)(xp + d4 * 4);
        acc += x4.x * w4.x + x4.y * w4.y + x4.z * w4.z + x4.w * w4.w;
    }
    g_qn[q * DMODEL + n] = acc + q_b[n];
}

// ---------------- in-place LayerNorm over rows of 768 ----------------
__global__ void ln_kernel(float* __restrict__ X,
                          const float* __restrict__ w,
                          const float* __restrict__ b) {
    int row = blockIdx.x;
    float* x = X + (size_t)row * DMODEL;
    int tid = threadIdx.x;
    float v0 = x[tid], v1 = x[tid + 256], v2 = x[tid + 512];
    float s = v0 + v1 + v2;
    float sq = v0 * v0 + v1 * v1 + v2 * v2;
    __shared__ float sbuf[16];
#pragma unroll
    for (int o = 16; o; o >>= 1) {
        s  += __shfl_xor_sync(0xffffffffu, s, o);
        sq += __shfl_xor_sync(0xffffffffu, sq, o);
    }
    int warp = tid >> 5, lane = tid & 31;
    if (lane == 0) { sbuf[warp] = s; sbuf[warp + 8] = sq; }
    __syncthreads();
    if (tid < 32) {
        float ss = (lane < 8) ? sbuf[lane] : 0.f;
        float qq = (lane < 8) ? sbuf[lane + 8] : 0.f;
#pragma unroll
        for (int o = 4; o; o >>= 1) {
            ss += __shfl_xor_sync(0xffffffffu, ss, o);
            qq += __shfl_xor_sync(0xffffffffu, qq, o);
        }
        if (lane == 0) { sbuf[0] = ss; sbuf[1] = qq; }
    }
    __syncthreads();
    float mean = sbuf[0] * (1.f / 768.f);
    float var  = sbuf[1] * (1.f / 768.f) - mean * mean;
    float rstd = rsqrtf(var + 1e-5f);
    x[tid]       = (v0 - mean) * rstd * w[tid]       + b[tid];
    x[tid + 256] = (v1 - mean) * rstd * w[tid + 256] + b[tid + 256];
    x[tid + 512] = (v2 - mean) * rstd * w[tid + 512] + b[tid + 512];
}

// ---------------- per-(side,i,head) attention partials ----------------
__global__ void attn_pre_kernel(const float* __restrict__ pos) {
    int i = blockIdx.x;      // 16
    int h = blockIdx.y;      // 12
    int side = blockIdx.z;   // 2
    __shared__ float sK[PTOK][33];
    __shared__ float sS[NQV][PTOK];
    __shared__ float sQ[NQV][64];
    int tid = threadIdx.x;
    int lane = tid & 31;
    int warp = tid >> 5;     // warp == qi (8 warps)

    for (int e = tid; e < NQV * 64; e += 256)
        sQ[e >> 6][e & 63] = g_qn[(e >> 6) * DMODEL + h * 64 + (e & 63)];

    float acc[7];
#pragma unroll
    for (int k = 0; k < 7; k++) acc[k] = 0.f;

    for (int c = 0; c < 2; c++) {
        __syncthreads();
        for (int e = tid; e < PTOK * 32; e += 256) {
            int p = e >> 5, d = e & 31;
            sK[p][d] = g_kvn[(size_t)(i * PTOK + p) * DMODEL + h * 64 + c * 32 + d]
                     + pos[(size_t)(side * PTOK + p) * DMODEL + h * 64 + c * 32 + d];
        }
        __syncthreads();
#pragma unroll
        for (int d = 0; d < 32; d++) {
            float qv = sQ[warp][c * 32 + d];
#pragma unroll
            for (int k = 0; k < 7; k++) {
                int p = lane + (k << 5);
                if (p < PTOK) acc[k] += sK[p][d] * qv;
            }
        }
    }

    float m = -INFINITY;
#pragma unroll
    for (int k = 0; k < 7; k++) {
        int p = lane + (k << 5);
        if (p < PTOK) m = fmaxf(m, acc[k] * 0.125f);
    }
#pragma unroll
    for (int o = 16; o; o >>= 1) m = fmaxf(m, __shfl_xor_sync(0xffffffffu, m, o));
    float ssum = 0.f;
#pragma unroll
    for (int k = 0; k < 7; k++) {
        int p = lane + (k << 5);
        if (p < PTOK) {
            float e = expf(acc[k] * 0.125f - m);
            sS[warp][p] = e;
            ssum += e;
        }
    }
#pragma unroll
    for (int o = 16; o; o >>= 1) ssum += __shfl_xor_sync(0xffffffffu, ssum, o);
    int sidx = ((side * BBATCH + i) * NHEADS + h) * NQV + warp;
    if (lane == 0) { g_m[sidx] = m; g_ssum[sidx] = ssum; }

    for (int c = 0; c < 2; c++) {
        __syncthreads();
        for (int e = tid; e < PTOK * 32; e += 256) {
            int p = e >> 5, d = e & 31;
            sK[p][d] = g_kvn[(size_t)(i * PTOK + p) * DMODEL + h * 64 + c * 32 + d]
                     + pos[(size_t)(side * PTOK + p) * DMODEL + h * 64 + c * 32 + d];
        }
        __syncthreads();
        float vacc = 0.f;
        for (int p = 0; p < PTOK; p++) vacc += sS[warp][p] * sK[p][lane];
        g_V[(size_t)sidx * 64 + c * 32 + lane] = vacc;
    }
}

// ---------------- per-pair renormalization coefficients ----------------
__global__ void coef_kernel() {
    int idx = blockIdx.x * 256 + threadIdx.x;   // 24576
    if (idx >= NPAIR * NHEADS * NQV) return;
    int qi = idx & 7;
    int h  = (idx >> 3) % NHEADS;
    int b  = idx / (NHEADS * NQV);
    int i = b >> 4, j = b & 15;
    int i1 = ((0 * BBATCH + i) * NHEADS + h) * NQV + qi;
    int i2 = ((1 * BBATCH + j) * NHEADS + h) * NQV + qi;
    float m1 = g_m[i1], m2 = g_m[i2];
    float s1 = g_ssum[i1], s2 = g_ssum[i2];
    float mm = fmaxf(m1, m2);
    float e1 = expf(m1 - mm), e2 = expf(m2 - mm);
    float inv = 1.f / (s1 * e1 + s2 * e2);
    g_ca[idx] = e1 * inv;
    g_cb[idx] = e2 * inv;
}

// ---------------- Y[si,h,q,:] = V[si,h,q,:] @ out_w[:, h*64:(h+1)*64]^T ------
// grid (32, 12, 6); block 128 (one n column per thread)
__global__ void ygemm_kernel(const float* __restrict__ out_w) {
    int si = blockIdx.x;     // side*16 + i
    int h  = blockIdx.y;
    int n0 = blockIdx.z * 128;
    int t  = threadIdx.x;
    __shared__ float sV[NQV][64];
    for (int e = t; e < NQV * 64; e += 128)
        sV[e >> 6][e & 63] = g_V[((size_t)(si * NHEADS + h) * NQV + (e >> 6)) * 64 + (e & 63)];
    __syncthreads();
    int n = n0 + t;
    const float* wp = out_w + (size_t)n * DMODEL + h * 64;
    float acc[NQV];
#pragma unroll
    for (int q = 0; q < NQV; q++) acc[q] = 0.f;
#pragma unroll
    for (int d4 = 0; d4 < 16; d4++) {
        float4 w4 = *(const float4*)(wp + d4 * 4);
#pragma unroll
        for (int q = 0; q < NQV; q++) {
            float4 v4 = *(const float4*)&sV[q][d4 * 4];
            acc[q] += v4.x * w4.x + v4.y * w4.y + v4.z * w4.z + v4.w * w4.w;
        }
    }
#pragma unroll
    for (int q = 0; q < NQV; q++)
        g_Y[((size_t)(si * NHEADS + h) * NQV + q) * DMODEL + n] = acc[q];
}

// ---------------- final: out[b,q,n] = sum_h ca*Y1 - cb*Y2 + out_b ----------
// grid 2048 (row), block 256, 3 columns per thread
__global__ void fcomb_kernel(const float* __restrict__ out_b,
                             float* __restrict__ out) {
    int row = blockIdx.x;          // b*8 + q
    int b = row >> 3, q = row & 7;
    int i = b >> 4, j = b & 15;
    int t = threadIdx.x;
    __shared__ float sca[NHEADS], scb[NHEADS];
    if (t < NHEADS) sca[t] = g_ca[(b * NHEADS + t) * NQV + q];
    else if (t < 2 * NHEADS) scb[t - NHEADS] = g_cb[(b * NHEADS + (t - NHEADS)) * NQV + q];
    __syncthreads();
    const size_t y1base = ((size_t)(i * NHEADS) * NQV + q) * DMODEL;
    const size_t y2base = ((size_t)((BBATCH + j) * NHEADS) * NQV + q) * DMODEL;
#pragma unroll
    for (int c = 0; c < 3; c++) {
        int n = t + c * 256;
        float acc = out_b[n];
#pragma unroll
        for (int h = 0; h < NHEADS; h++) {
            acc += sca[h] * g_Y[y1base + (size_t)h * NQV * DMODEL + n]
                 - scb[h] * g_Y[y2base + (size_t)h * NQV * DMODEL + n];
        }
        out[(size_t)row * DMODEL + n] = acc;
    }
}

// ---------------- launch ----------------
extern "C" void kernel_launch(void* const* d_in, const int* in_sizes, int n_in,
                              void* d_out, int out_size) {
    const float* q_x    = (const float*)d_in[0];
    const float* kv_x   = (const float*)d_in[1];
    const float* pos    = (const float*)d_in[2];
    const float* q_w    = (const float*)d_in[3];
    const float* q_b    = (const float*)d_in[4];
    const float* kv_w   = (const float*)d_in[5];
    const float* kv_b   = (const float*)d_in[6];
    const float* out_w  = (const float*)d_in[7];
    const float* out_b  = (const float*)d_in[8];
    const float* lnq_w  = (const float*)d_in[9];
    const float* lnq_b  = (const float*)d_in[10];
    const float* lnkv_w = (const float*)d_in[11];
    const float* lnkv_b = (const float*)d_in[12];
    float* out = (float*)d_out;

    float *qn, *kvn;
    cudaGetSymbolAddress((void**)&qn, g_qn);
    cudaGetSymbolAddress((void**)&kvn, g_kvn);

    // q path: small projection + LN (M=8)
    qproj_kernel<<<24, 256>>>(q_x, q_w, q_b);
    ln_kernel<<<NQV, 256>>>(qn, lnq_w, lnq_b);

    // kv path: f32x2 GEMM + LN (M=3152)
    gemm_f32x2_kernel<<<dim3((MKV + 127) / 128, 6), 256>>>(kv_x, kv_w, kv_b, kvn, MKV);
    ln_kernel<<<MKV, 256>>>(kvn, lnkv_w, lnkv_b);

    // per-(side,i,head) attention partials
    attn_pre_kernel<<<dim3(BBATCH, NHEADS, 2), 256>>>(pos);

    // pair renormalization coefficients
    coef_kernel<<<(NPAIR * NHEADS * NQV + 255) / 256, 256>>>();

    // per-(side,i,head) projected values: Y = V @ W_h^T  (302 MFLOP)
    ygemm_kernel<<<dim3(2 * BBATCH, NHEADS, 6), 128>>>(out_w);

    // final pairwise head-weighted combine straight into d_out
    fcomb_kernel<<<MOUT, 256>>>(out_b, out);
}